// round 3
// baseline (speedup 1.0000x reference)
#include <cuda_runtime.h>
#include <cstdint>

// Problem constants (fixed shapes from reference setup_inputs)
#define BB      16
#define NN      32768
#define CC      128
#define SS      1024
#define RCTAS   4                     // CTAs cooperating per batch
#define TPB     1024
#define PPC     (NN / RCTAS)          // points per CTA = 8192
#define PPT     (PPC / TPB)           // points per thread = 8
#define FLT_MAX_F 3.402823466e38f

typedef unsigned long long u64;
typedef unsigned int u32;

// ---------------------------------------------------------------------------
// Global scratch (all zero-initialized at module load; tags/done are restored
// to zero at the end of every kernel run -> graph-replay safe).
// ---------------------------------------------------------------------------
__device__ int    g_fps_idx[BB * SS];
__device__ float4 g_pay[BB][2][RCTAS];          // {v, x, y, z} per parity slot
__device__ u64    g_tag[BB][2][RCTAS];          // (idx<<32) | s  ; 0 = empty
__device__ u32    g_done[BB];

// ---------------------------------------------------------------------------
// FPS kernel: 4 plain CTAs per batch; coords + min_d live in registers.
// Cross-CTA exchange via tagged global mailbox (all CTAs wave-1 resident:
// grid = 64 <= 148 SMs, so spin-wait cannot deadlock).
// ---------------------------------------------------------------------------
__global__ void __launch_bounds__(TPB, 1)
fps_kernel(const float* __restrict__ p)
{
    const int t    = threadIdx.x;
    const int rank = blockIdx.x % RCTAS;
    const int b    = blockIdx.x / RCTAS;
    const int base = rank * PPC;

    const float* __restrict__ pb = p + (size_t)b * NN * 3;

    // Register-resident point coords and running min squared distance
    float px[PPT], py[PPT], pz[PPT], md[PPT];
#pragma unroll
    for (int k = 0; k < PPT; k++) {
        int n = base + k * TPB + t;
        px[k] = pb[n * 3 + 0];
        py[k] = pb[n * 3 + 1];
        pz[k] = pb[n * 3 + 2];
        md[k] = FLT_MAX_F;
    }

    // First selected point is index 0 (broadcast read of the same 12B)
    float qx = pb[0], qy = pb[1], qz = pb[2];
    if (rank == 0 && t == 0) g_fps_idx[b * SS + 0] = 0;

    // Per-warp block-reduce scratch (32 warps) + cross-CTA landing pads
    __shared__ float w_v[32], w_x[32], w_y[32], w_z[32];
    __shared__ int   w_i[32];
    __shared__ float m_v[RCTAS], m_x[RCTAS], m_y[RCTAS], m_z[RCTAS];
    __shared__ int   m_i[RCTAS];

    const int warp = t >> 5;
    const int lane = t & 31;

    for (int s = 1; s < SS; s++) {
        const int buf = s & 1;

        // ---- local update + per-thread argmax (tie-break: lowest index) ----
        float bv = -1.0f, bx = 0.f, by = 0.f, bz = 0.f;
        int   bi = 0x7fffffff;
#pragma unroll
        for (int k = 0; k < PPT; k++) {
            float dx = px[k] - qx;
            float dy = py[k] - qy;
            float dz = pz[k] - qz;
            float d  = fmaf(dz, dz, fmaf(dy, dy, dx * dx));
            float m  = fminf(md[k], d);
            md[k] = m;
            // strictly-greater keeps the earliest k (smallest index) on ties
            if (m > bv) { bv = m; bi = base + k * TPB + t; bx = px[k]; by = py[k]; bz = pz[k]; }
        }

        // ---- warp argmax reduce (payload: v, i, x, y, z) ----
#pragma unroll
        for (int off = 16; off > 0; off >>= 1) {
            float ov = __shfl_down_sync(0xffffffffu, bv, off);
            int   oi = __shfl_down_sync(0xffffffffu, bi, off);
            float ox = __shfl_down_sync(0xffffffffu, bx, off);
            float oy = __shfl_down_sync(0xffffffffu, by, off);
            float oz = __shfl_down_sync(0xffffffffu, bz, off);
            if (ov > bv || (ov == bv && oi < bi)) { bv = ov; bi = oi; bx = ox; by = oy; bz = oz; }
        }
        if (lane == 0) { w_v[warp] = bv; w_i[warp] = bi; w_x[warp] = bx; w_y[warp] = by; w_z[warp] = bz; }
        __syncthreads();

        // ---- warp 0: block reduce, publish, then gather all 4 CTA results ----
        if (warp == 0) {
            bv = w_v[lane]; bi = w_i[lane]; bx = w_x[lane]; by = w_y[lane]; bz = w_z[lane];
#pragma unroll
            for (int off = 16; off > 0; off >>= 1) {
                float ov = __shfl_down_sync(0xffffffffu, bv, off);
                int   oi = __shfl_down_sync(0xffffffffu, bi, off);
                float ox = __shfl_down_sync(0xffffffffu, bx, off);
                float oy = __shfl_down_sync(0xffffffffu, by, off);
                float oz = __shfl_down_sync(0xffffffffu, bz, off);
                if (ov > bv || (ov == bv && oi < bi)) { bv = ov; bi = oi; bx = ox; by = oy; bz = oz; }
            }
            if (lane == 0) {
                // publish: payload first, fence, then tag (tag == s marks valid)
                g_pay[b][buf][rank] = make_float4(bv, bx, by, bz);
                __threadfence();
                *(volatile u64*)&g_tag[b][buf][rank] =
                    ((u64)(u32)bi << 32) | (u64)(u32)s;
            }
            // lanes 0..3 each spin on one rank's tag, then pull its payload
            if (lane < RCTAS) {
                volatile u64* tp = (volatile u64*)&g_tag[b][buf][lane];
                u64 tag;
                do { tag = *tp; } while ((u32)tag != (u32)s);
                __threadfence();
                volatile float* pp = (volatile float*)&g_pay[b][buf][lane];
                m_v[lane] = pp[0];
                m_x[lane] = pp[1];
                m_y[lane] = pp[2];
                m_z[lane] = pp[3];
                m_i[lane] = (int)(tag >> 32);
            }
        }
        __syncthreads();

        // ---- every thread picks the batch-wide winner (lowest-index ties) ----
        float wv = m_v[0];
        int   wi = m_i[0];
        qx = m_x[0]; qy = m_y[0]; qz = m_z[0];
#pragma unroll
        for (int r = 1; r < RCTAS; r++) {
            float v = m_v[r];
            int   i = m_i[r];
            if (v > wv || (v == wv && i < wi)) {
                wv = v; wi = i;
                qx = m_x[r]; qy = m_y[r]; qz = m_z[r];
            }
        }
        if (rank == 0 && t == 0) g_fps_idx[b * SS + s] = wi;
        __syncthreads();   // protect w_* / m_* reuse next iteration
    }

    // ---- replay-safe cleanup: restore tags/done to zero ----
    if (t == 0) {
        __threadfence();
        atomicAdd(&g_done[b], 1u);
        if (rank == 0) {
            // wait until all 4 CTAs of this batch have finished all reads
            while (*(volatile u32*)&g_done[b] != RCTAS) { }
#pragma unroll
            for (int pb2 = 0; pb2 < 2; pb2++)
#pragma unroll
                for (int r = 0; r < RCTAS; r++)
                    *(volatile u64*)&g_tag[b][pb2][r] = 0ull;
            *(volatile u32*)&g_done[b] = 0u;
            __threadfence();
        }
    }
}

// ---------------------------------------------------------------------------
// Gather kernel: out = [p_out (B*S*3) | x_out (B*C*S)]
// ---------------------------------------------------------------------------
__global__ void gather_kernel(const float* __restrict__ p,
                              const float* __restrict__ x,
                              float* __restrict__ out)
{
    const int tid = blockIdx.x * blockDim.x + threadIdx.x;

    // x_out: [B, C, S] with coalesced writes over s
    if (tid < BB * CC * SS) {
        int s = tid % SS;
        int c = (tid / SS) % CC;
        int b = tid / (SS * CC);
        int idx = g_fps_idx[b * SS + s];
        out[(size_t)BB * SS * 3 + tid] = x[((size_t)b * CC + c) * NN + idx];
    }

    // p_out: [B, S, 3]
    if (tid < BB * SS) {
        int b = tid / SS;
        int idx = g_fps_idx[tid];
        const float* src = p + ((size_t)b * NN + idx) * 3;
        out[tid * 3 + 0] = src[0];
        out[tid * 3 + 1] = src[1];
        out[tid * 3 + 2] = src[2];
    }
}

// ---------------------------------------------------------------------------
// Harness entry
// ---------------------------------------------------------------------------
extern "C" void kernel_launch(void* const* d_in, const int* in_sizes, int n_in,
                              void* d_out, int out_size)
{
    const float* p = (const float*)d_in[0];   // [B, N, 3]
    const float* x = (const float*)d_in[1];   // [B, C, N]
    float* out = (float*)d_out;

    fps_kernel<<<BB * RCTAS, TPB>>>(p);

    const int total = BB * CC * SS;
    gather_kernel<<<(total + 255) / 256, 256>>>(p, x, out);
}

// round 4
// speedup vs baseline: 1.6457x; 1.6457x over previous
#include <cuda_runtime.h>
#include <cstdint>

// Problem constants (fixed shapes from reference setup_inputs)
#define BB      16
#define NN      32768
#define CC      128
#define SS      1024
#define RCTAS   4                     // CTAs cooperating per batch
#define TPB     1024
#define PPC     (NN / RCTAS)          // points per CTA = 8192
#define PPT     (PPC / TPB)           // points per thread = 8
#define FLT_MAX_F 3.402823466e38f

typedef unsigned long long u64;
typedef unsigned int u32;

// ---------------------------------------------------------------------------
// Global scratch. g_key slots are restored to zero at end of kernel -> graph
// replay safe (tag low 16 bits: s in [1,1023], 0 never matches).
// Message format: (v_bits << 32) | ((idx ^ 0x7FFF) << 16) | s
//   v >= 0 so float bits are order-preserving; idx inverted so max() picks
//   the LOWEST index on distance ties; low 16 bits tag the iteration.
// ---------------------------------------------------------------------------
__device__ int g_fps_idx[BB * SS];
__device__ u64 g_key[BB][2][RCTAS];
__device__ u32 g_done[BB];

__device__ __forceinline__ u64 pack_key(float v, int idx, int s) {
    return ((u64)__float_as_uint(v) << 32)
         | ((u64)(u32)(idx ^ 0x7FFF) << 16)
         | (u64)(u32)s;
}

// ---------------------------------------------------------------------------
// FPS: 4 plain CTAs per batch; coords + min_d live in registers.
// Cross-CTA exchange = one volatile 64-bit word per CTA per iteration.
// Grid = 64 CTAs <= 148 SMs -> all wave-1 resident, spin cannot deadlock.
// ---------------------------------------------------------------------------
__global__ void __launch_bounds__(TPB, 1)
fps_kernel(const float* __restrict__ p)
{
    const int t    = threadIdx.x;
    const int rank = blockIdx.x % RCTAS;
    const int b    = blockIdx.x / RCTAS;
    const int base = rank * PPC;

    const float* __restrict__ pb = p + (size_t)b * NN * 3;

    // Register-resident point coords and running min squared distance
    float px[PPT], py[PPT], pz[PPT], md[PPT];
#pragma unroll
    for (int k = 0; k < PPT; k++) {
        int n = base + k * TPB + t;
        px[k] = pb[n * 3 + 0];
        py[k] = pb[n * 3 + 1];
        pz[k] = pb[n * 3 + 2];
        md[k] = FLT_MAX_F;
    }

    // First selected point is index 0
    float qx = pb[0], qy = pb[1], qz = pb[2];
    if (rank == 0 && t == 0) g_fps_idx[b * SS + 0] = 0;

    __shared__ u64 w_key[32];        // per-warp reduce scratch
    __shared__ u64 m_key[RCTAS];     // cross-CTA landing pad

    const int warp = t >> 5;
    const int lane = t & 31;

    for (int s = 1; s < SS; s++) {
        const int buf = s & 1;

        // ---- local update + per-thread argmax (tie-break: lowest k/index) ----
        float bv = -1.0f;
        int   bk = 0;
#pragma unroll
        for (int k = 0; k < PPT; k++) {
            float dx = px[k] - qx;
            float dy = py[k] - qy;
            float dz = pz[k] - qz;
            float d  = fmaf(dz, dz, fmaf(dy, dy, dx * dx));
            float m  = fminf(md[k], d);
            md[k] = m;
            if (m > bv) { bv = m; bk = k; }   // strict >: earliest k on ties
        }
        u64 key = pack_key(bv, base + bk * TPB + t, s);

        // ---- warp argmax reduce: max of packed keys ----
#pragma unroll
        for (int off = 16; off > 0; off >>= 1) {
            u64 ok = __shfl_down_sync(0xffffffffu, key, off);
            if (ok > key) key = ok;
        }
        if (lane == 0) w_key[warp] = key;
        __syncthreads();

        // ---- warp 0: block reduce (32 warps), publish, gather ----
        if (warp == 0) {
            key = w_key[lane];
#pragma unroll
            for (int off = 16; off > 0; off >>= 1) {
                u64 ok = __shfl_down_sync(0xffffffffu, key, off);
                if (ok > key) key = ok;
            }
            if (lane == 0)
                *(volatile u64*)&g_key[b][buf][rank] = key;   // single-word msg
            if (lane < RCTAS) {
                volatile u64* tp = (volatile u64*)&g_key[b][buf][lane];
                u64 k2;
                do { k2 = *tp; } while ((u32)(k2 & 0xFFFFu) != (u32)s);
                m_key[lane] = k2;
            }
        }
        __syncthreads();

        // ---- every thread: batch-wide winner, re-fetch its coords ----
        u64 wk = m_key[0];
        if (m_key[1] > wk) wk = m_key[1];
        if (m_key[2] > wk) wk = m_key[2];
        if (m_key[3] > wk) wk = m_key[3];
        int wi = 0x7FFF ^ (int)((wk >> 16) & 0x7FFFu);

        qx = pb[wi * 3 + 0];          // broadcast LDG, L2-resident
        qy = pb[wi * 3 + 1];
        qz = pb[wi * 3 + 2];
        if (rank == 0 && t == 0) g_fps_idx[b * SS + s] = wi;
    }

    // ---- replay-safe cleanup: restore key slots to zero ----
    if (t == 0) {
        __threadfence();
        atomicAdd(&g_done[b], 1u);
        if (rank == 0) {
            while (*(volatile u32*)&g_done[b] != RCTAS) { }
#pragma unroll
            for (int pb2 = 0; pb2 < 2; pb2++)
#pragma unroll
                for (int r = 0; r < RCTAS; r++)
                    *(volatile u64*)&g_key[b][pb2][r] = 0ull;
            *(volatile u32*)&g_done[b] = 0u;
            __threadfence();
        }
    }
}

// ---------------------------------------------------------------------------
// Gather kernel: out = [p_out (B*S*3) | x_out (B*C*S)]  (already ~HBM roofline)
// ---------------------------------------------------------------------------
__global__ void gather_kernel(const float* __restrict__ p,
                              const float* __restrict__ x,
                              float* __restrict__ out)
{
    const int tid = blockIdx.x * blockDim.x + threadIdx.x;

    if (tid < BB * CC * SS) {
        int s = tid % SS;
        int c = (tid / SS) % CC;
        int b = tid / (SS * CC);
        int idx = g_fps_idx[b * SS + s];
        out[(size_t)BB * SS * 3 + tid] = x[((size_t)b * CC + c) * NN + idx];
    }

    if (tid < BB * SS) {
        int b = tid / SS;
        int idx = g_fps_idx[tid];
        const float* src = p + ((size_t)b * NN + idx) * 3;
        out[tid * 3 + 0] = src[0];
        out[tid * 3 + 1] = src[1];
        out[tid * 3 + 2] = src[2];
    }
}

// ---------------------------------------------------------------------------
// Harness entry
// ---------------------------------------------------------------------------
extern "C" void kernel_launch(void* const* d_in, const int* in_sizes, int n_in,
                              void* d_out, int out_size)
{
    const float* p = (const float*)d_in[0];   // [B, N, 3]
    const float* x = (const float*)d_in[1];   // [B, C, N]
    float* out = (float*)d_out;

    fps_kernel<<<BB * RCTAS, TPB>>>(p);

    const int total = BB * CC * SS;
    gather_kernel<<<(total + 255) / 256, 256>>>(p, x, out);
}